// round 1
// baseline (speedup 1.0000x reference)
#include <cuda_runtime.h>
#include <cstdint>

// Problem constants
#define M_DIM 4096
#define N_DIM 32000
#define K_DIM 128
#define BM 128
#define BN 256
#define KP 132   // padded k-stride in smem words (conflict-free: 132 % 32 == 4)

// Device scratch (static allocation is allowed; cudaMalloc is not)
__device__ float g_summed[M_DIM * K_DIM];          // 2 MB
__device__ float g_W[N_DIM * K_DIM];               // 16.4 MB, TF32-rounded copy of W
__device__ int   g_stride;                         // 1 = int32 indices, 2 = int64

__device__ __forceinline__ unsigned f2tf32(float f) {
    unsigned u;
    asm("cvt.rna.tf32.f32 %0, %1;" : "=r"(u) : "f"(f));
    return u;
}

// ---------------------------------------------------------------------------
// Detect whether x is int64 or int32. If int64 (little-endian), every odd
// 32-bit word within the first 32768 words is a zero high-word. A genuine
// int32 index array (values uniform in [0,32000)) has ~0 probability of
// 16384 zeros at odd positions.
// ---------------------------------------------------------------------------
__global__ void detect_kernel(const int* __restrict__ x32) {
    __shared__ int any;
    if (threadIdx.x == 0) any = 0;
    __syncthreads();
    int found = 0;
    for (int i = 1 + 2 * threadIdx.x; i < 32768; i += 512)
        if (x32[i] != 0) found = 1;
    if (found) any = 1;   // benign race: only 1 is ever written
    __syncthreads();
    if (threadIdx.x == 0) g_stride = any ? 1 : 2;
}

// ---------------------------------------------------------------------------
// Pre-round W to TF32 so the GEMM mainloop has no CVT instructions.
// 32000*128/4 = 1,024,000 float4 -> grid 4000 x 256
// ---------------------------------------------------------------------------
__global__ void round_w_kernel(const float4* __restrict__ W) {
    int i = blockIdx.x * 256 + threadIdx.x;
    float4 v = W[i];
    uint4 u;
    u.x = f2tf32(v.x); u.y = f2tf32(v.y);
    u.z = f2tf32(v.z); u.w = f2tf32(v.w);
    reinterpret_cast<uint4*>(g_W)[i] = u;
}

// ---------------------------------------------------------------------------
// CBOW gather-sum: summed[b] = sum_{c, idx!=0} emb[idx[b][c]]  (TF32-rounded)
// One warp per sample, float4 per lane. grid 512 x 256.
// ---------------------------------------------------------------------------
__global__ void sum_emb_kernel(const int* __restrict__ x32,
                               const float4* __restrict__ emb) {
    int sample = blockIdx.x * 8 + (threadIdx.x >> 5);
    int v = threadIdx.x & 31;
    int stride = g_stride;
    float4 s = make_float4(0.f, 0.f, 0.f, 0.f);
#pragma unroll
    for (int c = 0; c < 8; c++) {
        int i = x32[(sample * 8 + c) * stride];   // low word if int64
        if (i != 0) {                              // padding_idx = 0
            float4 t = emb[i * 32 + v];
            s.x += t.x; s.y += t.y; s.z += t.z; s.w += t.w;
        }
    }
    uint4 u;
    u.x = f2tf32(s.x); u.y = f2tf32(s.y);
    u.z = f2tf32(s.z); u.w = f2tf32(s.w);
    reinterpret_cast<uint4*>(g_summed)[sample * 32 + v] = u;
}

// ---------------------------------------------------------------------------
// GEMM: out[M,N] = summed[M,K] @ W[N,K]^T + b
// CTA tile 128x256, 8 warps (2x4) each computing 64x64 via m16n8k8 TF32 mma.
// K=128 loaded entirely into smem (no k-pipeline needed).
// Smem: A[128][132] + B[256][132] words = 202,752 B (dynamic, opt-in).
// ---------------------------------------------------------------------------
__global__ void __launch_bounds__(256, 1)
gemm_kernel(const float* __restrict__ bias, float* __restrict__ out) {
    extern __shared__ unsigned smem[];
    unsigned* As = smem;              // [128][132]
    unsigned* Bs = smem + BM * KP;    // [256][132]

    const int tid = threadIdx.x;
    const int bm = blockIdx.y * BM;
    const int bn = blockIdx.x * BN;

    // Fill A tile: 128 rows x 32 uint4
    const uint4* Ag = reinterpret_cast<const uint4*>(g_summed) + bm * 32;
#pragma unroll
    for (int it = 0; it < 16; it++) {
        int idx = tid + it * 256;
        int row = idx >> 5, j = idx & 31;
        uint4 v = Ag[idx];
        *reinterpret_cast<uint4*>(&As[row * KP + j * 4]) = v;
    }
    // Fill B tile: 256 rows x 32 uint4
    const uint4* Bg = reinterpret_cast<const uint4*>(g_W) + bn * 32;
#pragma unroll
    for (int it = 0; it < 32; it++) {
        int idx = tid + it * 256;
        int row = idx >> 5, j = idx & 31;
        uint4 v = Bg[idx];
        *reinterpret_cast<uint4*>(&Bs[row * KP + j * 4]) = v;
    }
    __syncthreads();

    const int lane = tid & 31;
    const int warp = tid >> 5;
    const int wm = (warp & 1) * 64;    // 2 warps along M
    const int wn = (warp >> 1) * 64;   // 4 warps along N
    const int g  = lane >> 2;          // 0..7
    const int tg = lane & 3;           // 0..3

    float acc[4][8][4];
#pragma unroll
    for (int mi = 0; mi < 4; mi++)
#pragma unroll
        for (int ni = 0; ni < 8; ni++)
#pragma unroll
            for (int r = 0; r < 4; r++) acc[mi][ni][r] = 0.f;

#pragma unroll 4
    for (int ks = 0; ks < 16; ks++) {
        int k0 = ks * 8;
        unsigned a[4][4], b[8][2];
#pragma unroll
        for (int mi = 0; mi < 4; mi++) {
            int r0 = (wm + mi * 16 + g) * KP + k0 + tg;
            a[mi][0] = As[r0];
            a[mi][1] = As[r0 + 8 * KP];
            a[mi][2] = As[r0 + 4];
            a[mi][3] = As[r0 + 8 * KP + 4];
        }
#pragma unroll
        for (int ni = 0; ni < 8; ni++) {
            int c0 = (wn + ni * 8 + g) * KP + k0 + tg;
            b[ni][0] = Bs[c0];
            b[ni][1] = Bs[c0 + 4];
        }
#pragma unroll
        for (int mi = 0; mi < 4; mi++)
#pragma unroll
            for (int ni = 0; ni < 8; ni++)
                asm volatile(
                    "mma.sync.aligned.m16n8k8.row.col.f32.tf32.tf32.f32 "
                    "{%0,%1,%2,%3}, {%4,%5,%6,%7}, {%8,%9}, {%0,%1,%2,%3};"
                    : "+f"(acc[mi][ni][0]), "+f"(acc[mi][ni][1]),
                      "+f"(acc[mi][ni][2]), "+f"(acc[mi][ni][3])
                    : "r"(a[mi][0]), "r"(a[mi][1]), "r"(a[mi][2]), "r"(a[mi][3]),
                      "r"(b[ni][0]), "r"(b[ni][1]));
    }

    // Epilogue: bias add + float2 stores. Tiles divide exactly; no bounds checks.
#pragma unroll
    for (int ni = 0; ni < 8; ni++) {
        int col = bn + wn + ni * 8 + 2 * tg;
        float2 bb = *reinterpret_cast<const float2*>(bias + col);
#pragma unroll
        for (int mi = 0; mi < 4; mi++) {
            int row = bm + wm + mi * 16 + g;
            float2 v0 = make_float2(acc[mi][ni][0] + bb.x, acc[mi][ni][1] + bb.y);
            float2 v1 = make_float2(acc[mi][ni][2] + bb.x, acc[mi][ni][3] + bb.y);
            *reinterpret_cast<float2*>(out + (size_t)row * N_DIM + col) = v0;
            *reinterpret_cast<float2*>(out + (size_t)(row + 8) * N_DIM + col) = v1;
        }
    }
}

// ---------------------------------------------------------------------------
extern "C" void kernel_launch(void* const* d_in, const int* in_sizes, int n_in,
                              void* d_out, int out_size) {
    const int*   x    = (const int*)d_in[0];     // int32 or low-words of int64
    const float* emb  = (const float*)d_in[1];
    const float* W    = (const float*)d_in[2];
    const float* bias = (const float*)d_in[3];
    float* out = (float*)d_out;

    (void)in_sizes; (void)n_in; (void)out_size;

    static const size_t smem_bytes = (size_t)(BM + BN) * KP * 4;
    cudaFuncSetAttribute(gemm_kernel,
                         cudaFuncAttributeMaxDynamicSharedMemorySize,
                         (int)smem_bytes);

    detect_kernel<<<1, 256>>>(x);
    round_w_kernel<<<N_DIM * K_DIM / 4 / 256, 256>>>((const float4*)W);
    sum_emb_kernel<<<M_DIM / 8, 256>>>(x, (const float4*)emb);

    dim3 grid(N_DIM / BN, M_DIM / BM);
    gemm_kernel<<<grid, 256, smem_bytes>>>(bias, out);
}